// round 2
// baseline (speedup 1.0000x reference)
#include <cuda_runtime.h>
#include <math.h>

#define Ndim 8192
#define Fdim 128
#define Fo   64
#define Hh   4
#define BM   128
#define BK   32

// ---------------- scratch (device globals; no allocation allowed) ----------------
__device__ float g_Xp[Hh * Ndim * Fo];   // projected features [H][N][Fo]
__device__ float g_ss[Hh * Ndim];        // s_self
__device__ float g_sn[Hh * Ndim];        // s_neigh
__device__ float g_P [Hh * Ndim];        // exp(s_self - c)
__device__ float g_Pn[Hh * Ndim];        // exp(0.2*s_self - c)
__device__ float g_Q [Hh * Ndim];        // exp(s_neigh)
__device__ float g_Qn[Hh * Ndim];        // exp(0.2*s_neigh)
__device__ float g_mx[Hh];               // max_m s_neigh per head

// ---------------- kernel 1: Xp[h,n,d] = sum_f X[n,f] * W[h,f,d] ----------------
__global__ void proj_kernel(const float* __restrict__ X, const float* __restrict__ W) {
    int idx = blockIdx.x * blockDim.x + threadIdx.x;   // H*N*Fo = 2^21 threads
    int d = idx & (Fo - 1);
    int n = (idx >> 6) & (Ndim - 1);
    int h = idx >> 19;
    const float* Wh = W + (h * Fdim) * Fo + d;
    const float* Xr = X + n * Fdim;
    float acc = 0.f;
#pragma unroll 16
    for (int f = 0; f < Fdim; ++f)
        acc = fmaf(__ldg(Xr + f), __ldg(Wh + f * Fo), acc);
    g_Xp[(h * Ndim + n) * Fo + d] = acc;
}

// ---------------- kernel 2: attention score halves ----------------
__global__ void score_kernel(const float* __restrict__ a_self, const float* __restrict__ a_neigh) {
    int idx = blockIdx.x * blockDim.x + threadIdx.x;   // H*N
    int h = idx >> 13;
    const float* xp = g_Xp + (size_t)idx * Fo;
    float s1 = 0.f, s2 = 0.f;
#pragma unroll 16
    for (int d = 0; d < Fo; ++d) {
        float v = xp[d];
        s1 = fmaf(v, __ldg(a_self + h * Fo + d), s1);
        s2 = fmaf(v, __ldg(a_neigh + h * Fo + d), s2);
    }
    g_ss[idx] = s1;
    g_sn[idx] = s2;
}

// ---------------- kernel 3: per-head max of s_neigh ----------------
__global__ void max_kernel() {
    __shared__ float sm[256];
    int h = blockIdx.x, t = threadIdx.x;
    float m = -1e30f;
    for (int i = t; i < Ndim; i += 256) m = fmaxf(m, g_sn[h * Ndim + i]);
    sm[t] = m;
    __syncthreads();
    for (int s = 128; s > 0; s >>= 1) {
        if (t < s) sm[t] = fmaxf(sm[t], sm[t + s]);
        __syncthreads();
    }
    if (t == 0) g_mx[h] = sm[0];
}

// ---------------- kernel 4: exp tables ----------------
__global__ void pq_kernel() {
    int idx = blockIdx.x * blockDim.x + threadIdx.x;   // H*N
    int h = idx >> 13;
    float ss = g_ss[idx], sn = g_sn[idx];
    float tmx = ss + g_mx[h];
    float c = tmx > 0.f ? tmx : 0.2f * tmx;           // lrelu(s_self + max s_neigh) >= row max
    g_P [idx] = expf(ss - c);
    g_Pn[idx] = expf(0.2f * ss - c);
    g_Q [idx] = expf(sn);
    g_Qn[idx] = expf(0.2f * sn);
}

// ---------------- main: fused weight-gen + weighted GEMM + softmax-normalize ----------------
__global__ __launch_bounds__(256, 2)
void gat_main(const float* __restrict__ A, float* __restrict__ out) {
    __shared__ __align__(16) float sW[BK][BM + 4];     // weight tile, [k][row], pad to dodge conflicts
    __shared__ __align__(16) float sXp[BK][Fo];        // Xp tile [k][d]
    __shared__ float sP[BM], sPn[BM], sS[BM];
    __shared__ float sQ[BK], sQn[BK], sT[BK];
    __shared__ float sDen[2 * BM];

    int t  = threadIdx.x;
    int h  = blockIdx.y;
    int n0 = blockIdx.x * BM;
    int tx = t & 15, ty = t >> 4;

    if (t < BM) {
        int g = h * Ndim + n0 + t;
        sP[t] = g_P[g]; sPn[t] = g_Pn[g]; sS[t] = g_ss[g];
    }

    float acc[8][4];
#pragma unroll
    for (int r = 0; r < 8; ++r)
#pragma unroll
        for (int c = 0; c < 4; ++c) acc[r][c] = 0.f;

    float dpart = 0.f;
    int drow = t >> 1, dhalf = (t & 1) * 16;

    const float4* A4  = reinterpret_cast<const float4*>(A);
    const float4* Xp4 = reinterpret_cast<const float4*>(g_Xp + (size_t)h * Ndim * Fo);

    for (int m0 = 0; m0 < Ndim; m0 += BK) {
        __syncthreads();   // previous GEMM done reading smem
        if (t < BK) {
            int g = h * Ndim + m0 + t;
            sQ[t] = g_Q[g]; sQn[t] = g_Qn[g]; sT[t] = g_sn[g];
        }
        // Xp tile: 32x64 floats = 512 float4
#pragma unroll
        for (int r = 0; r < 2; ++r) {
            int e = t + 256 * r;
            int k = e >> 4, dq = e & 15;
            float4 v = __ldg(Xp4 + (size_t)(m0 + k) * (Fo / 4) + dq);
            *reinterpret_cast<float4*>(&sXp[k][dq * 4]) = v;
        }
        __syncthreads();   // sQ/sQn/sT visible to ALL threads before weight-gen reads them
        // weight tile: 128x32 = 1024 float4 of A
#pragma unroll
        for (int r = 0; r < 4; ++r) {
            int j = t + 256 * r;
            int i = j >> 3, q = j & 7;
            float4 a = __ldg(A4 + (size_t)(n0 + i) * (Ndim / 4) + (m0 >> 2) + q);
            float ss = sS[i], P = sP[i], Pn = sPn[i];
            int kb = q * 4;
            float tt0 = ss + sT[kb + 0];
            float tt1 = ss + sT[kb + 1];
            float tt2 = ss + sT[kb + 2];
            float tt3 = ss + sT[kb + 3];
            float w0 = (tt0 > 0.f ? P * sQ[kb + 0] : Pn * sQn[kb + 0]) * a.x;
            float w1 = (tt1 > 0.f ? P * sQ[kb + 1] : Pn * sQn[kb + 1]) * a.y;
            float w2 = (tt2 > 0.f ? P * sQ[kb + 2] : Pn * sQn[kb + 2]) * a.z;
            float w3 = (tt3 > 0.f ? P * sQ[kb + 3] : Pn * sQn[kb + 3]) * a.w;
            sW[kb + 0][i] = w0;
            sW[kb + 1][i] = w1;
            sW[kb + 2][i] = w2;
            sW[kb + 3][i] = w3;
        }
        __syncthreads();   // sW/sXp visible before GEMM
        // register-tiled GEMM: C[128x64] += W[128x32] * Xp[32x64]
#pragma unroll
        for (int k = 0; k < BK; ++k) {
            float4 wlo = *reinterpret_cast<const float4*>(&sW[k][ty * 8]);
            float4 whi = *reinterpret_cast<const float4*>(&sW[k][ty * 8 + 4]);
            float4 xp  = *reinterpret_cast<const float4*>(&sXp[k][tx * 4]);
            float wf[8] = {wlo.x, wlo.y, wlo.z, wlo.w, whi.x, whi.y, whi.z, whi.w};
#pragma unroll
            for (int r = 0; r < 8; ++r) {
                acc[r][0] = fmaf(wf[r], xp.x, acc[r][0]);
                acc[r][1] = fmaf(wf[r], xp.y, acc[r][1]);
                acc[r][2] = fmaf(wf[r], xp.z, acc[r][2]);
                acc[r][3] = fmaf(wf[r], xp.w, acc[r][3]);
            }
        }
        // denominator partial: row-sum of weight tile (2 threads per row, 16 k's each)
#pragma unroll
        for (int kk = 0; kk < 16; ++kk) dpart += sW[dhalf + kk][drow];
    }

    __syncthreads();
    sDen[t] = dpart;          // t = drow*2 + half
    __syncthreads();

#pragma unroll
    for (int r = 0; r < 8; ++r) {
        int row = ty * 8 + r;
        float den = sDen[row * 2] + sDen[row * 2 + 1];
        float inv = 1.0f / den;
        float4 o;
        o.x = fmaxf(acc[r][0] * inv, 0.f);
        o.y = fmaxf(acc[r][1] * inv, 0.f);
        o.z = fmaxf(acc[r][2] * inv, 0.f);
        o.w = fmaxf(acc[r][3] * inv, 0.f);
        *reinterpret_cast<float4*>(out + (size_t)(n0 + row) * (Hh * Fo) + h * Fo + tx * 4) = o;
    }
}

// ---------------- launcher ----------------
extern "C" void kernel_launch(void* const* d_in, const int* in_sizes, int n_in,
                              void* d_out, int out_size) {
    const float* X       = (const float*)d_in[0];   // [8192,128]
    const float* A       = (const float*)d_in[1];   // [8192,8192]
    const float* W       = (const float*)d_in[2];   // [4,128,64]
    const float* a_self  = (const float*)d_in[3];   // [4,64]
    const float* a_neigh = (const float*)d_in[4];   // [4,64]
    float* out = (float*)d_out;                     // [8192, 256]

    proj_kernel <<<(Hh * Ndim * Fo) / 256, 256>>>(X, W);
    score_kernel<<<(Hh * Ndim) / 256, 256>>>(a_self, a_neigh);
    max_kernel  <<<Hh, 256>>>();
    pq_kernel   <<<(Hh * Ndim) / 256, 256>>>();

    dim3 grid(Ndim / BM, Hh);
    gat_main<<<grid, 256>>>(A, out);
}

// round 5
// speedup vs baseline: 2.3488x; 2.3488x over previous
#include <cuda_runtime.h>
#include <cuda_fp16.h>
#include <math.h>
#include <stdint.h>

#define Ndim 8192
#define Fdim 128
#define Fo   64
#define Hh   4
#define NC   72          // operand cols per side: 64 feats + 1 denom + 7 pad
#define BKT  64          // k per tile
#define NTILE (Ndim / BKT)

// ---------------- scratch ----------------
__device__ __align__(16) float  g_Xp[Hh * Ndim * Fo];
__device__ __align__(16) float  g_ss[Hh * Ndim];
__device__ __align__(16) float  g_sn[Hh * Ndim];
__device__ __align__(16) float  g_P [Hh * Ndim];
__device__ __align__(16) float  g_Pn[Hh * Ndim];
__device__ __align__(16) float  g_Q [Hh * Ndim];
__device__ __align__(16) float  g_Qn[Hh * Ndim];
__device__ float g_mx[Hh];
// fp16 operand tables [h][side][col NC][m 8192]; side0 = Q'-scaled, side1 = Qn'-scaled
__device__ __align__(16) __half g_Y[Hh * 2 * NC * Ndim];

// ---------------- helpers ----------------
__device__ __forceinline__ uint32_t smem_u32(const void* p) {
    uint32_t a;
    asm("{ .reg .u64 t; cvta.to.shared.u64 t, %1; cvt.u32.u64 %0, t; }" : "=r"(a) : "l"(p));
    return a;
}
#define SWZ128(x) ((x) ^ (((x) >> 3) & 0x70))

__device__ __forceinline__ void ldsm4(uint32_t* r, uint32_t a) {
    asm volatile("ldmatrix.sync.aligned.m8n8.x4.shared.b16 {%0,%1,%2,%3}, [%4];"
        : "=r"(r[0]), "=r"(r[1]), "=r"(r[2]), "=r"(r[3]) : "r"(a));
}
__device__ __forceinline__ void ldsm2(uint32_t* r, uint32_t a) {
    asm volatile("ldmatrix.sync.aligned.m8n8.x2.shared.b16 {%0,%1}, [%2];"
        : "=r"(r[0]), "=r"(r[1]) : "r"(a));
}
__device__ __forceinline__ void mma16816(float* d, const uint32_t* a, const uint32_t* b) {
    asm volatile("mma.sync.aligned.m16n8k16.row.col.f32.f16.f16.f32 "
        "{%0,%1,%2,%3}, {%4,%5,%6,%7}, {%8,%9}, {%0,%1,%2,%3};"
        : "+f"(d[0]), "+f"(d[1]), "+f"(d[2]), "+f"(d[3])
        : "r"(a[0]), "r"(a[1]), "r"(a[2]), "r"(a[3]), "r"(b[0]), "r"(b[1]));
}
__device__ __forceinline__ void cp16(uint32_t smaddr, const void* gaddr) {
    asm volatile("cp.async.cg.shared.global [%0], [%1], 16;" :: "r"(smaddr), "l"(gaddr));
}
#define CP_COMMIT() asm volatile("cp.async.commit_group;" ::: "memory")
#define CP_WAIT0()  asm volatile("cp.async.wait_group 0;" ::: "memory")

// ---------------- kernel 1: tiled projection Xp = X @ W[h] ----------------
__global__ __launch_bounds__(256)
void proj_kernel(const float* __restrict__ X, const float* __restrict__ W) {
    __shared__ float sX[64][65];
    __shared__ float sW[64][64];
    int t = threadIdx.x;
    int n0 = blockIdx.x * 64, h = blockIdx.y;
    int tc = t & 15, tr = t >> 4;
    float acc[4][4];
#pragma unroll
    for (int r = 0; r < 4; ++r)
#pragma unroll
        for (int c = 0; c < 4; ++c) acc[r][c] = 0.f;

    for (int k0 = 0; k0 < Fdim; k0 += 64) {
        __syncthreads();
#pragma unroll
        for (int r = 0; r < 4; ++r) {
            int idx = t + 256 * r;
            int row = idx >> 4, kq = idx & 15;
            float4 v = __ldg((const float4*)(X + (size_t)(n0 + row) * Fdim + k0) + kq);
            sX[row][kq * 4 + 0] = v.x;    // scalar stores: row stride 65 floats is NOT
            sX[row][kq * 4 + 1] = v.y;    // 16B-aligned, float4 store here traps
            sX[row][kq * 4 + 2] = v.z;
            sX[row][kq * 4 + 3] = v.w;
        }
#pragma unroll
        for (int r = 0; r < 4; ++r) {
            int idx = t + 256 * r;
            int row = idx >> 4, kq = idx & 15;
            *(float4*)&sW[row][kq * 4] =
                __ldg((const float4*)(W + ((size_t)(h * Fdim) + k0 + row) * Fo) + kq);
        }
        __syncthreads();
#pragma unroll 16
        for (int kk = 0; kk < 64; ++kk) {
            float4 wv = *(const float4*)&sW[kk][tc * 4];
            float xv0 = sX[tr * 4 + 0][kk];
            float xv1 = sX[tr * 4 + 1][kk];
            float xv2 = sX[tr * 4 + 2][kk];
            float xv3 = sX[tr * 4 + 3][kk];
#define PR(r, xv) \
            acc[r][0] = fmaf(xv, wv.x, acc[r][0]); \
            acc[r][1] = fmaf(xv, wv.y, acc[r][1]); \
            acc[r][2] = fmaf(xv, wv.z, acc[r][2]); \
            acc[r][3] = fmaf(xv, wv.w, acc[r][3]);
            PR(0, xv0) PR(1, xv1) PR(2, xv2) PR(3, xv3)
#undef PR
        }
    }
#pragma unroll
    for (int r = 0; r < 4; ++r) {
        float4 o = make_float4(acc[r][0], acc[r][1], acc[r][2], acc[r][3]);
        *(float4*)(g_Xp + ((size_t)(h * Ndim + n0 + tr * 4 + r)) * Fo + tc * 4) = o;
    }
}

// ---------------- kernel 2: score halves ----------------
__global__ void score_kernel(const float* __restrict__ a_self, const float* __restrict__ a_neigh) {
    int idx = blockIdx.x * blockDim.x + threadIdx.x;   // H*N
    int h = idx >> 13;
    const float* xp = g_Xp + (size_t)idx * Fo;
    float s1 = 0.f, s2 = 0.f;
#pragma unroll 16
    for (int d = 0; d < Fo; ++d) {
        float v = xp[d];
        s1 = fmaf(v, __ldg(a_self + h * Fo + d), s1);
        s2 = fmaf(v, __ldg(a_neigh + h * Fo + d), s2);
    }
    g_ss[idx] = s1;
    g_sn[idx] = s2;
}

// ---------------- kernel 3: per-head max of s_neigh ----------------
__global__ void max_kernel() {
    __shared__ float sm[256];
    int h = blockIdx.x, t = threadIdx.x;
    float m = -1e30f;
    for (int i = t; i < Ndim; i += 256) m = fmaxf(m, g_sn[h * Ndim + i]);
    sm[t] = m;
    __syncthreads();
    for (int s = 128; s > 0; s >>= 1) {
        if (t < s) sm[t] = fmaxf(sm[t], sm[t + s]);
        __syncthreads();
    }
    if (t == 0) g_mx[h] = sm[0];
}

// ---------------- kernel 4: exp tables (range-managed for fp16) ----------------
__global__ void pq_kernel() {
    int idx = blockIdx.x * blockDim.x + threadIdx.x;   // H*N
    int h = idx >> 13;
    float ss = g_ss[idx], sn = g_sn[idx];
    float mx = g_mx[h];
    float cm = mx > 0.f ? mx : 0.2f * mx;             // lrelu(mx): Q',Qn' <= 1
    float tmx = ss + mx;
    float ci = tmx > 0.f ? tmx : 0.2f * tmx;          // row stabilizer
    g_P [idx] = expf(ss - ci);
    g_Pn[idx] = expf(0.2f * ss - ci);
    g_Q [idx] = expf(sn - cm);
    g_Qn[idx] = expf(0.2f * sn - cm);
}

// ---------------- kernel 5: fp16 operand tables ----------------
__global__ __launch_bounds__(256)
void y_kernel() {
    __shared__ float sXp[64][65];
    __shared__ float sQ[64], sQn[64];
    int t = threadIdx.x;
    int m0 = blockIdx.x * 64, h = blockIdx.y;

#pragma unroll
    for (int r = 0; r < 4; ++r) {
        int idx = t + 256 * r;
        int j = idx >> 4, dq = idx & 15;
        float4 v = __ldg((const float4*)(g_Xp + ((size_t)(h * Ndim + m0 + j)) * Fo) + dq);
        sXp[j][dq * 4 + 0] = v.x;
        sXp[j][dq * 4 + 1] = v.y;
        sXp[j][dq * 4 + 2] = v.z;
        sXp[j][dq * 4 + 3] = v.w;
    }
    if (t < 64) {
        sQ[t]  = g_Q [h * Ndim + m0 + t];
        sQn[t] = g_Qn[h * Ndim + m0 + t];
    }
    __syncthreads();

    for (int idx = t; idx < 2 * NC * 8; idx += 256) {   // chunks of 8 halfs
        int side = idx >= NC * 8;
        int l = side ? idx - NC * 8 : idx;
        int row = l >> 3, g8 = l & 7;
        ushort u[8];
#pragma unroll
        for (int p = 0; p < 8; ++p) {
            int m = g8 * 8 + p;
            float q = side ? sQn[m] : sQ[m];
            float v = (row < 64) ? q * sXp[m][row] : (row == 64 ? q : 0.f);
            u[p] = __half_as_ushort(__float2half_rn(v));
        }
        uint4 pk;
        pk.x = (uint32_t)u[0] | ((uint32_t)u[1] << 16);
        pk.y = (uint32_t)u[2] | ((uint32_t)u[3] << 16);
        pk.z = (uint32_t)u[4] | ((uint32_t)u[5] << 16);
        pk.w = (uint32_t)u[6] | ((uint32_t)u[7] << 16);
        *(uint4*)(g_Y + ((size_t)((h * 2 + side) * NC + row)) * Ndim + m0 + g8 * 8) = pk;
    }
}

// ---------------- main kernel: masked fp16 HMMA GEMM ----------------
// dyn smem layout (1024-aligned base):
//   header 4096: sSS@0, sP@512, sPn@1024, sInv@1536
//   stage[buf] @ 4096 + buf*51200:
//     S_B=0 (16KB maskB), S_C=16384 (16KB maskC), S_YB=32768 (9216), S_YC=41984 (9216)
//   epilogue scratch reuses stage area: scB@4096 (128x76 f32), scC@4096+40960
#define HDR    4096
#define S_B    0
#define S_C    16384
#define S_YB   32768
#define S_YC   41984
#define STAGE  51200
#define SMEM_DYN (1024 + HDR + 2 * STAGE)
#define NCP    76

__global__ __launch_bounds__(256, 1)
void gat_mma(const float* __restrict__ A, float* __restrict__ out) {
    extern __shared__ char dsm[];
    uint32_t sb0 = smem_u32(dsm);
    uint32_t sb = (sb0 + 1023u) & ~1023u;
    char* smp = dsm + (sb - sb0);

    int t = threadIdx.x, wid = t >> 5, lane = t & 31;
    int h = blockIdx.y, n0 = blockIdx.x * 128;

    float* sSS  = (float*)(smp + 0);
    float* sP   = (float*)(smp + 512);
    float* sPn  = (float*)(smp + 1024);
    float* sInv = (float*)(smp + 1536);
    if (t < 128) {
        int g = h * Ndim + n0 + t;
        sSS[t] = g_ss[g];
        sP[t]  = g_P[g];
        sPn[t] = g_Pn[g];
    }
    __syncthreads();

    const float4* A4 = (const float4*)A;
    int q  = t & 15;      // float4 col in k-tile
    int i0 = t >> 4;      // base row (rows i0 + 16r)

    // ---- prologue: stage 0 ----
    {
        int m0 = 0;
        uint32_t st = HDR;
        for (int idx = t; idx < 2 * NC * 8; idx += 256) {
            int side = idx >= NC * 8;
            int l = side ? idx - NC * 8 : idx;
            int row = l >> 3, kq = l & 7;
            const __half* gp = g_Y + ((size_t)((h * 2 + side) * NC + row)) * Ndim + m0 + kq * 8;
            cp16(sb + st + (side ? S_YC : S_YB) + SWZ128((uint32_t)(row * 128 + kq * 16)), gp);
        }
        CP_COMMIT();
        float4 snv = __ldg((const float4*)(g_sn + h * Ndim + m0) + q);
        float4 av[8];
#pragma unroll
        for (int r = 0; r < 8; ++r)
            av[r] = __ldg(A4 + (size_t)(n0 + i0 + 16 * r) * (Ndim / 4) + (m0 >> 2) + q);
#pragma unroll
        for (int r = 0; r < 8; ++r) {
            int i = i0 + 16 * r;
            float ss = sSS[i];
            float t0 = ss + snv.x, t1 = ss + snv.y, t2 = ss + snv.z, t3 = ss + snv.w;
            bool e0 = av[r].x != 0.f, e1 = av[r].y != 0.f, e2 = av[r].z != 0.f, e3 = av[r].w != 0.f;
            const uint32_t HONE = 0x3C00u;
            uint32_t b01 = ((e0 && t0 > 0.f) ? HONE : 0u) | (((e1 && t1 > 0.f) ? HONE : 0u) << 16);
            uint32_t b23 = ((e2 && t2 > 0.f) ? HONE : 0u) | (((e3 && t3 > 0.f) ? HONE : 0u) << 16);
            uint32_t c01 = ((e0 && t0 <= 0.f) ? HONE : 0u) | (((e1 && t1 <= 0.f) ? HONE : 0u) << 16);
            uint32_t c23 = ((e2 && t2 <= 0.f) ? HONE : 0u) | (((e3 && t3 <= 0.f) ? HONE : 0u) << 16);
            uint32_t off = SWZ128((uint32_t)(i * 128 + q * 8));
            *(uint2*)(smp + st + S_B + off) = make_uint2(b01, b23);
            *(uint2*)(smp + st + S_C + off) = make_uint2(c01, c23);
        }
        CP_WAIT0();
        __syncthreads();
    }

    // warp work assignment
    int side = wid >> 2;          // 0: B-side (P), 1: C-side (Pn)
    int rg   = wid & 3;
    int row0 = rg * 32;
    int la15 = lane & 15, la7 = lane & 7;
    uint32_t aRow  = (uint32_t)(row0 + la15) * 128 + ((lane >> 4) ? 16u : 0u);
    uint32_t bRow  = (uint32_t)la7 * 128 + (((lane >> 3) & 1) ? 16u : 0u);

    float acc[2][9][4];
#pragma unroll
    for (int rt = 0; rt < 2; ++rt)
#pragma unroll
        for (int nt = 0; nt < 9; ++nt)
#pragma unroll
            for (int c = 0; c < 4; ++c) acc[rt][nt][c] = 0.f;

    // ---- main loop ----
    for (int tile = 0; tile < NTILE; ++tile) {
        int cur = tile & 1;
        uint32_t stc = HDR + cur * STAGE;
        uint32_t stn = HDR + (cur ^ 1) * STAGE;
        int m1 = (tile + 1) * BKT;

        float4 av[8];
        float4 snv;
        if (tile < NTILE - 1) {
            for (int idx = t; idx < 2 * NC * 8; idx += 256) {
                int sd = idx >= NC * 8;
                int l = sd ? idx - NC * 8 : idx;
                int row = l >> 3, kq = l & 7;
                const __half* gp = g_Y + ((size_t)((h * 2 + sd) * NC + row)) * Ndim + m1 + kq * 8;
                cp16(sb + stn + (sd ? S_YC : S_YB) + SWZ128((uint32_t)(row * 128 + kq * 16)), gp);
            }
            CP_COMMIT();
            snv = __ldg((const float4*)(g_sn + h * Ndim + m1) + q);
#pragma unroll
            for (int r = 0; r < 8; ++r)
                av[r] = __ldg(A4 + (size_t)(n0 + i0 + 16 * r) * (Ndim / 4) + (m1 >> 2) + q);
        }

        // ---- mma on current stage ----
        uint32_t mbase = sb + stc + (side ? S_C : S_B);
        uint32_t ybase = sb + stc + (side ? S_YC : S_YB);
#pragma unroll
        for (int ks = 0; ks < 4; ++ks) {
            uint32_t a0[4], a1[4];
            ldsm4(a0, mbase + SWZ128(aRow + ks * 32));
            ldsm4(a1, mbase + SWZ128(aRow + 2048 + ks * 32));
#pragma unroll
            for (int nt = 0; nt < 9; ++nt) {
                uint32_t b[2];
                ldsm2(b, ybase + SWZ128(bRow + (uint32_t)nt * 1024 + ks * 32));
                mma16816(acc[0][nt], a0, b);
                mma16816(acc[1][nt], a1, b);
            }
        }

        if (tile < NTILE - 1) {
#pragma unroll
            for (int r = 0; r < 8; ++r) {
                int i = i0 + 16 * r;
                float ss = sSS[i];
                float t0 = ss + snv.x, t1 = ss + snv.y, t2 = ss + snv.z, t3 = ss + snv.w;
                bool e0 = av[r].x != 0.f, e1 = av[r].y != 0.f, e2 = av[r].z != 0.f, e3 = av[r].w != 0.f;
                const uint32_t HONE = 0x3C00u;
                uint32_t b01 = ((e0 && t0 > 0.f) ? HONE : 0u) | (((e1 && t1 > 0.f) ? HONE : 0u) << 16);
                uint32_t b23 = ((e2 && t2 > 0.f) ? HONE : 0u) | (((e3 && t3 > 0.f) ? HONE : 0u) << 16);
                uint32_t c01 = ((e0 && t0 <= 0.f) ? HONE : 0u) | (((e1 && t1 <= 0.f) ? HONE : 0u) << 16);
                uint32_t c23 = ((e2 && t2 <= 0.f) ? HONE : 0u) | (((e3 && t3 <= 0.f) ? HONE : 0u) << 16);
                uint32_t off = SWZ128((uint32_t)(i * 128 + q * 8));
                *(uint2*)(smp + stn + S_B + off) = make_uint2(b01, b23);
                *(uint2*)(smp + stn + S_C + off) = make_uint2(c01, c23);
            }
            CP_WAIT0();
        }
        __syncthreads();
    }

    // ---- epilogue ----
    float* sc = (float*)(smp + HDR + (side ? 40960 : 0));
#pragma unroll
    for (int rt = 0; rt < 2; ++rt)
#pragma unroll
        for (int nt = 0; nt < 9; ++nt) {
            int row = row0 + rt * 16 + (lane >> 2);
            int col = nt * 8 + (lane & 3) * 2;
            *(float2*)&sc[row * NCP + col]       = make_float2(acc[rt][nt][0], acc[rt][nt][1]);
            *(float2*)&sc[(row + 8) * NCP + col] = make_float2(acc[rt][nt][2], acc[rt][nt][3]);
        }
    __syncthreads();

    float* scB = (float*)(smp + HDR);
    float* scC = (float*)(smp + HDR + 40960);
    if (t < 128) {
        float den = sP[t] * scB[t * NCP + 64] + sPn[t] * scC[t * NCP + 64];
        sInv[t] = 1.0f / den;
    }
    __syncthreads();

    for (int idx = t; idx < 128 * 64; idx += 256) {
        int row = idx >> 6, col = idx & 63;
        float v = (sP[row] * scB[row * NCP + col] + sPn[row] * scC[row * NCP + col]) * sInv[row];
        out[(size_t)(n0 + row) * (Hh * Fo) + h * Fo + col] = fmaxf(v, 0.f);
    }
}

// ---------------- launcher ----------------
extern "C" void kernel_launch(void* const* d_in, const int* in_sizes, int n_in,
                              void* d_out, int out_size) {
    const float* X       = (const float*)d_in[0];
    const float* A       = (const float*)d_in[1];
    const float* W       = (const float*)d_in[2];
    const float* a_self  = (const float*)d_in[3];
    const float* a_neigh = (const float*)d_in[4];
    float* out = (float*)d_out;

    cudaFuncSetAttribute(gat_mma, cudaFuncAttributeMaxDynamicSharedMemorySize, SMEM_DYN);

    proj_kernel <<<dim3(Ndim / 64, Hh), 256>>>(X, W);
    score_kernel<<<(Hh * Ndim) / 256, 256>>>(a_self, a_neigh);
    max_kernel  <<<Hh, 256>>>();
    pq_kernel   <<<(Hh * Ndim) / 256, 256>>>();
    y_kernel    <<<dim3(Ndim / 64, Hh), 256>>>();

    gat_mma<<<dim3(Ndim / 128, Hh), 256, SMEM_DYN>>>(A, out);
}

// round 6
// speedup vs baseline: 3.2643x; 1.3897x over previous
#include <cuda_runtime.h>
#include <cuda_fp16.h>
#include <math.h>
#include <stdint.h>

#define Ndim 8192
#define Fdim 128
#define Fo   64
#define Hh   4
#define NC   72          // operand cols per side: 64 feats + 1 denom + 7 pad
#define BKT  64          // k per tile
#define NTILE (Ndim / BKT)

// ---------------- scratch ----------------
__device__ __align__(16) float  g_Xp[Hh * Ndim * Fo];
__device__ __align__(16) float  g_ss[Hh * Ndim];
__device__ __align__(16) float  g_sn[Hh * Ndim];
__device__ __align__(16) __half g_snh[Hh * Ndim];   // fp16 copy of s_neigh for mask gen
__device__ __align__(16) float  g_P [Hh * Ndim];
__device__ __align__(16) float  g_Pn[Hh * Ndim];
__device__ __align__(16) float  g_Q [Hh * Ndim];
__device__ __align__(16) float  g_Qn[Hh * Ndim];
__device__ float g_mx[Hh];
// fp16 operand tables [h][side][col NC][m 8192]; side0 = Q'-scaled, side1 = Qn'-scaled
__device__ __align__(16) __half g_Y[Hh * 2 * NC * Ndim];

// ---------------- helpers ----------------
__device__ __forceinline__ uint32_t smem_u32(const void* p) {
    uint32_t a;
    asm("{ .reg .u64 t; cvta.to.shared.u64 t, %1; cvt.u32.u64 %0, t; }" : "=r"(a) : "l"(p));
    return a;
}
#define SWZ128(x) ((x) ^ (((x) >> 3) & 0x70))

__device__ __forceinline__ void ldsm4(uint32_t* r, uint32_t a) {
    asm volatile("ldmatrix.sync.aligned.m8n8.x4.shared.b16 {%0,%1,%2,%3}, [%4];"
        : "=r"(r[0]), "=r"(r[1]), "=r"(r[2]), "=r"(r[3]) : "r"(a));
}
__device__ __forceinline__ void ldsm2(uint32_t* r, uint32_t a) {
    asm volatile("ldmatrix.sync.aligned.m8n8.x2.shared.b16 {%0,%1}, [%2];"
        : "=r"(r[0]), "=r"(r[1]) : "r"(a));
}
__device__ __forceinline__ void mma16816(float* d, const uint32_t* a, const uint32_t* b) {
    asm volatile("mma.sync.aligned.m16n8k16.row.col.f32.f16.f16.f32 "
        "{%0,%1,%2,%3}, {%4,%5,%6,%7}, {%8,%9}, {%0,%1,%2,%3};"
        : "+f"(d[0]), "+f"(d[1]), "+f"(d[2]), "+f"(d[3])
        : "r"(a[0]), "r"(a[1]), "r"(a[2]), "r"(a[3]), "r"(b[0]), "r"(b[1]));
}
__device__ __forceinline__ void cp16(uint32_t smaddr, const void* gaddr) {
    asm volatile("cp.async.cg.shared.global [%0], [%1], 16;" :: "r"(smaddr), "l"(gaddr));
}
#define CP_COMMIT() asm volatile("cp.async.commit_group;" ::: "memory")
#define CP_WAIT0()  asm volatile("cp.async.wait_group 0;" ::: "memory")

// ---------------- kernel 1: tiled projection Xp = X @ W[h] ----------------
__global__ __launch_bounds__(256)
void proj_kernel(const float* __restrict__ X, const float* __restrict__ W) {
    __shared__ float sX[64][65];
    __shared__ float sW[64][64];
    int t = threadIdx.x;
    int n0 = blockIdx.x * 64, h = blockIdx.y;
    int tc = t & 15, tr = t >> 4;
    float acc[4][4];
#pragma unroll
    for (int r = 0; r < 4; ++r)
#pragma unroll
        for (int c = 0; c < 4; ++c) acc[r][c] = 0.f;

    for (int k0 = 0; k0 < Fdim; k0 += 64) {
        __syncthreads();
#pragma unroll
        for (int r = 0; r < 4; ++r) {
            int idx = t + 256 * r;
            int row = idx >> 4, kq = idx & 15;
            float4 v = __ldg((const float4*)(X + (size_t)(n0 + row) * Fdim + k0) + kq);
            sX[row][kq * 4 + 0] = v.x;    // scalar stores (row stride 65: not 16B aligned)
            sX[row][kq * 4 + 1] = v.y;
            sX[row][kq * 4 + 2] = v.z;
            sX[row][kq * 4 + 3] = v.w;
        }
#pragma unroll
        for (int r = 0; r < 4; ++r) {
            int idx = t + 256 * r;
            int row = idx >> 4, kq = idx & 15;
            *(float4*)&sW[row][kq * 4] =
                __ldg((const float4*)(W + ((size_t)(h * Fdim) + k0 + row) * Fo) + kq);
        }
        __syncthreads();
#pragma unroll 16
        for (int kk = 0; kk < 64; ++kk) {
            float4 wv = *(const float4*)&sW[kk][tc * 4];
            float xv0 = sX[tr * 4 + 0][kk];
            float xv1 = sX[tr * 4 + 1][kk];
            float xv2 = sX[tr * 4 + 2][kk];
            float xv3 = sX[tr * 4 + 3][kk];
#define PR(r, xv) \
            acc[r][0] = fmaf(xv, wv.x, acc[r][0]); \
            acc[r][1] = fmaf(xv, wv.y, acc[r][1]); \
            acc[r][2] = fmaf(xv, wv.z, acc[r][2]); \
            acc[r][3] = fmaf(xv, wv.w, acc[r][3]);
            PR(0, xv0) PR(1, xv1) PR(2, xv2) PR(3, xv3)
#undef PR
        }
    }
#pragma unroll
    for (int r = 0; r < 4; ++r) {
        float4 o = make_float4(acc[r][0], acc[r][1], acc[r][2], acc[r][3]);
        *(float4*)(g_Xp + ((size_t)(h * Ndim + n0 + tr * 4 + r)) * Fo + tc * 4) = o;
    }
}

// ---------------- kernel 2: score halves ----------------
__global__ void score_kernel(const float* __restrict__ a_self, const float* __restrict__ a_neigh) {
    int idx = blockIdx.x * blockDim.x + threadIdx.x;   // H*N
    int h = idx >> 13;
    const float* xp = g_Xp + (size_t)idx * Fo;
    float s1 = 0.f, s2 = 0.f;
#pragma unroll 16
    for (int d = 0; d < Fo; ++d) {
        float v = xp[d];
        s1 = fmaf(v, __ldg(a_self + h * Fo + d), s1);
        s2 = fmaf(v, __ldg(a_neigh + h * Fo + d), s2);
    }
    g_ss[idx] = s1;
    g_sn[idx] = s2;
}

// ---------------- kernel 3: per-head max of s_neigh ----------------
__global__ void max_kernel() {
    __shared__ float sm[256];
    int h = blockIdx.x, t = threadIdx.x;
    float m = -1e30f;
    for (int i = t; i < Ndim; i += 256) m = fmaxf(m, g_sn[h * Ndim + i]);
    sm[t] = m;
    __syncthreads();
    for (int s = 128; s > 0; s >>= 1) {
        if (t < s) sm[t] = fmaxf(sm[t], sm[t + s]);
        __syncthreads();
    }
    if (t == 0) g_mx[h] = sm[0];
}

// ---------------- kernel 4: exp tables (range-managed for fp16) ----------------
__global__ void pq_kernel() {
    int idx = blockIdx.x * blockDim.x + threadIdx.x;   // H*N
    int h = idx >> 13;
    float ss = g_ss[idx], sn = g_sn[idx];
    float mx = g_mx[h];
    float cm = mx > 0.f ? mx : 0.2f * mx;             // lrelu(mx): Q',Qn' <= 1
    float tmx = ss + mx;
    float ci = tmx > 0.f ? tmx : 0.2f * tmx;          // row stabilizer
    g_P [idx] = expf(ss - ci);
    g_Pn[idx] = expf(0.2f * ss - ci);
    g_Q [idx] = expf(sn - cm);
    g_Qn[idx] = expf(0.2f * sn - cm);
    g_snh[idx] = __float2half_rn(sn);
}

// ---------------- kernel 5: fp16 operand tables ----------------
__global__ __launch_bounds__(256)
void y_kernel() {
    __shared__ float sXp[64][65];
    __shared__ float sQ[64], sQn[64];
    int t = threadIdx.x;
    int m0 = blockIdx.x * 64, h = blockIdx.y;

#pragma unroll
    for (int r = 0; r < 4; ++r) {
        int idx = t + 256 * r;
        int j = idx >> 4, dq = idx & 15;
        float4 v = __ldg((const float4*)(g_Xp + ((size_t)(h * Ndim + m0 + j)) * Fo) + dq);
        sXp[j][dq * 4 + 0] = v.x;
        sXp[j][dq * 4 + 1] = v.y;
        sXp[j][dq * 4 + 2] = v.z;
        sXp[j][dq * 4 + 3] = v.w;
    }
    if (t < 64) {
        sQ[t]  = g_Q [h * Ndim + m0 + t];
        sQn[t] = g_Qn[h * Ndim + m0 + t];
    }
    __syncthreads();

    for (int idx = t; idx < 2 * NC * 8; idx += 256) {   // chunks of 8 halfs
        int side = idx >= NC * 8;
        int l = side ? idx - NC * 8 : idx;
        int row = l >> 3, g8 = l & 7;
        ushort u[8];
#pragma unroll
        for (int p = 0; p < 8; ++p) {
            int m = g8 * 8 + p;
            float q = side ? sQn[m] : sQ[m];
            float v = (row < 64) ? q * sXp[m][row] : (row == 64 ? q : 0.f);
            u[p] = __half_as_ushort(__float2half_rn(v));
        }
        uint4 pk;
        pk.x = (uint32_t)u[0] | ((uint32_t)u[1] << 16);
        pk.y = (uint32_t)u[2] | ((uint32_t)u[3] << 16);
        pk.z = (uint32_t)u[4] | ((uint32_t)u[5] << 16);
        pk.w = (uint32_t)u[6] | ((uint32_t)u[7] << 16);
        *(uint4*)(g_Y + ((size_t)((h * 2 + side) * NC + row)) * Ndim + m0 + g8 * 8) = pk;
    }
}

// ---------------- main kernel: masked fp16 HMMA GEMM ----------------
#define HDR    4096
#define S_B    0
#define S_C    16384
#define S_YB   32768
#define S_YC   41984
#define STAGE  51200
#define SMEM_DYN (1024 + HDR + 2 * STAGE)
#define NCP    76

__global__ __launch_bounds__(256, 1)
void gat_mma(const float* __restrict__ A, float* __restrict__ out) {
    extern __shared__ char dsm[];
    uint32_t sb0 = smem_u32(dsm);
    uint32_t sb = (sb0 + 1023u) & ~1023u;
    char* smp = dsm + (sb - sb0);

    int t = threadIdx.x, wid = t >> 5, lane = t & 31;
    int h = blockIdx.y, n0 = blockIdx.x * 128;

    float* sSS  = (float*)(smp + 0);
    float* sP   = (float*)(smp + 512);
    float* sPn  = (float*)(smp + 1024);
    float* sInv = (float*)(smp + 1536);
    if (t < 128) {
        int g = h * Ndim + n0 + t;
        sSS[t] = g_ss[g];
        sP[t]  = g_P[g];
        sPn[t] = g_Pn[g];
    }
    __syncthreads();

    const float4* A4 = (const float4*)A;
    int q  = t & 15;      // float4 col in k-tile
    int i0 = t >> 4;      // base row (rows i0 + 16r)

    // broadcast fp16 self-scores for the 8 rows this thread masks
    __half2 ssh[8];
#pragma unroll
    for (int r = 0; r < 8; ++r) ssh[r] = __float2half2_rn(sSS[i0 + 16 * r]);
    const __half2 hzero = __float2half2_rn(0.f);

    // ---- prologue: stage 0 ----
    {
        int m0 = 0;
        uint32_t st = HDR;
        for (int idx = t; idx < 2 * NC * 8; idx += 256) {
            int side = idx >= NC * 8;
            int l = side ? idx - NC * 8 : idx;
            int row = l >> 3, kq = l & 7;
            const __half* gp = g_Y + ((size_t)((h * 2 + side) * NC + row)) * Ndim + m0 + kq * 8;
            cp16(sb + st + (side ? S_YC : S_YB) + SWZ128((uint32_t)(row * 128 + kq * 16)), gp);
        }
        CP_COMMIT();
        uint2 snp = *(const uint2*)(g_snh + h * Ndim + m0 + q * 4);
        __half2 sn01 = *(__half2*)&snp.x, sn23 = *(__half2*)&snp.y;
        float4 av[8];
#pragma unroll
        for (int r = 0; r < 8; ++r)
            av[r] = __ldg(A4 + (size_t)(n0 + i0 + 16 * r) * (Ndim / 4) + (m0 >> 2) + q);
#pragma unroll
        for (int r = 0; r < 8; ++r) {
            int i = i0 + 16 * r;
            __half2 a01 = __floats2half2_rn(av[r].x, av[r].y);
            __half2 a23 = __floats2half2_rn(av[r].z, av[r].w);
            __half2 b01 = __hmul2(a01, __hgt2(__hadd2(ssh[r], sn01), hzero));
            __half2 b23 = __hmul2(a23, __hgt2(__hadd2(ssh[r], sn23), hzero));
            __half2 c01 = __hsub2(a01, b01);
            __half2 c23 = __hsub2(a23, b23);
            uint32_t off = SWZ128((uint32_t)(i * 128 + q * 8));
            *(uint2*)(smp + st + S_B + off) = make_uint2(*(uint32_t*)&b01, *(uint32_t*)&b23);
            *(uint2*)(smp + st + S_C + off) = make_uint2(*(uint32_t*)&c01, *(uint32_t*)&c23);
        }
        CP_WAIT0();
        __syncthreads();
    }

    // warp work assignment
    int side = wid >> 2;          // 0: B-side (P), 1: C-side (Pn)
    int rg   = wid & 3;
    int row0 = rg * 32;
    int la15 = lane & 15, la7 = lane & 7;
    uint32_t aRow  = (uint32_t)(row0 + la15) * 128 + ((lane >> 4) ? 16u : 0u);
    uint32_t bRow  = (uint32_t)la7 * 128 + (((lane >> 3) & 1) ? 16u : 0u);
    uint32_t bRow4 = bRow + (uint32_t)(lane >> 4) * 1024;   // x4: lanes 16-31 -> next n-tile

    float acc[2][9][4];
#pragma unroll
    for (int rt = 0; rt < 2; ++rt)
#pragma unroll
        for (int nt = 0; nt < 9; ++nt)
#pragma unroll
            for (int c = 0; c < 4; ++c) acc[rt][nt][c] = 0.f;

    // ---- main loop ----
    for (int tile = 0; tile < NTILE; ++tile) {
        int cur = tile & 1;
        uint32_t stc = HDR + cur * STAGE;
        uint32_t stn = HDR + (cur ^ 1) * STAGE;
        int m1 = (tile + 1) * BKT;

        float4 av[8];
        __half2 sn01, sn23;
        if (tile < NTILE - 1) {
            for (int idx = t; idx < 2 * NC * 8; idx += 256) {
                int sd = idx >= NC * 8;
                int l = sd ? idx - NC * 8 : idx;
                int row = l >> 3, kq = l & 7;
                const __half* gp = g_Y + ((size_t)((h * 2 + sd) * NC + row)) * Ndim + m1 + kq * 8;
                cp16(sb + stn + (sd ? S_YC : S_YB) + SWZ128((uint32_t)(row * 128 + kq * 16)), gp);
            }
            CP_COMMIT();
            uint2 snp = *(const uint2*)(g_snh + h * Ndim + m1 + q * 4);
            sn01 = *(__half2*)&snp.x;
            sn23 = *(__half2*)&snp.y;
#pragma unroll
            for (int r = 0; r < 8; ++r)
                av[r] = __ldg(A4 + (size_t)(n0 + i0 + 16 * r) * (Ndim / 4) + (m1 >> 2) + q);
        }

        // ---- mma on current stage ----
        uint32_t mbase = sb + stc + (side ? S_C : S_B);
        uint32_t ybase = sb + stc + (side ? S_YC : S_YB);
#pragma unroll
        for (int ks = 0; ks < 4; ++ks) {
            uint32_t a0[4], a1[4];
            ldsm4(a0, mbase + SWZ128(aRow + ks * 32));
            ldsm4(a1, mbase + SWZ128(aRow + 2048 + ks * 32));
#pragma unroll
            for (int np = 0; np < 4; ++np) {        // n-tile pairs (0,1)..(6,7) via x4
                uint32_t b4[4];
                ldsm4(b4, ybase + SWZ128(bRow4 + (uint32_t)np * 2048 + ks * 32));
                mma16816(acc[0][np * 2 + 0], a0, b4);
                mma16816(acc[1][np * 2 + 0], a1, b4);
                mma16816(acc[0][np * 2 + 1], a0, b4 + 2);
                mma16816(acc[1][np * 2 + 1], a1, b4 + 2);
            }
            {                                       // n-tile 8 via x2
                uint32_t b[2];
                ldsm2(b, ybase + SWZ128(bRow + 8u * 1024 + ks * 32));
                mma16816(acc[0][8], a0, b);
                mma16816(acc[1][8], a1, b);
            }
        }

        if (tile < NTILE - 1) {
#pragma unroll
            for (int r = 0; r < 8; ++r) {
                int i = i0 + 16 * r;
                __half2 a01 = __floats2half2_rn(av[r].x, av[r].y);
                __half2 a23 = __floats2half2_rn(av[r].z, av[r].w);
                __half2 b01 = __hmul2(a01, __hgt2(__hadd2(ssh[r], sn01), hzero));
                __half2 b23 = __hmul2(a23, __hgt2(__hadd2(ssh[r], sn23), hzero));
                __half2 c01 = __hsub2(a01, b01);
                __half2 c23 = __hsub2(a23, b23);
                uint32_t off = SWZ128((uint32_t)(i * 128 + q * 8));
                *(uint2*)(smp + stn + S_B + off) = make_uint2(*(uint32_t*)&b01, *(uint32_t*)&b23);
                *(uint2*)(smp + stn + S_C + off) = make_uint2(*(uint32_t*)&c01, *(uint32_t*)&c23);
            }
            CP_WAIT0();
        }
        __syncthreads();
    }

    // ---- epilogue ----
    float* sc = (float*)(smp + HDR + (side ? 40960 : 0));
#pragma unroll
    for (int rt = 0; rt < 2; ++rt)
#pragma unroll
        for (int nt = 0; nt < 9; ++nt) {
            int row = row0 + rt * 16 + (lane >> 2);
            int col = nt * 8 + (lane & 3) * 2;
            *(float2*)&sc[row * NCP + col]       = make_float2(acc[rt][nt][0], acc[rt][nt][1]);
            *(float2*)&sc[(row + 8) * NCP + col] = make_float2(acc[rt][nt][2], acc[rt][nt][3]);
        }
    __syncthreads();

    float* scB = (float*)(smp + HDR);
    float* scC = (float*)(smp + HDR + 40960);
    if (t < 128) {
        float den = sP[t] * scB[t * NCP + 64] + sPn[t] * scC[t * NCP + 64];
        sInv[t] = 1.0f / den;
    }
    __syncthreads();

    for (int idx = t; idx < 128 * 64; idx += 256) {
        int row = idx >> 6, col = idx & 63;
        float v = (sP[row] * scB[row * NCP + col] + sPn[row] * scC[row * NCP + col]) * sInv[row];
        out[(size_t)(n0 + row) * (Hh * Fo) + h * Fo + col] = fmaxf(v, 0.f);
    }
}

// ---------------- launcher ----------------
extern "C" void kernel_launch(void* const* d_in, const int* in_sizes, int n_in,
                              void* d_out, int out_size) {
    const float* X       = (const float*)d_in[0];
    const float* A       = (const float*)d_in[1];
    const float* W       = (const float*)d_in[2];
    const float* a_self  = (const float*)d_in[3];
    const float* a_neigh = (const float*)d_in[4];
    float* out = (float*)d_out;

    cudaFuncSetAttribute(gat_mma, cudaFuncAttributeMaxDynamicSharedMemorySize, SMEM_DYN);

    proj_kernel <<<dim3(Ndim / 64, Hh), 256>>>(X, W);
    score_kernel<<<(Hh * Ndim) / 256, 256>>>(a_self, a_neigh);
    max_kernel  <<<Hh, 256>>>();
    pq_kernel   <<<(Hh * Ndim) / 256, 256>>>();
    y_kernel    <<<dim3(Ndim / 64, Hh), 256>>>();

    gat_mma<<<dim3(Ndim / 128, Hh), 256, SMEM_DYN>>>(A, out);
}